// round 16
// baseline (speedup 1.0000x reference)
#include <cuda_runtime.h>
#include <cuda_fp16.h>
#include <cstdint>

#define SSn 2048
#define DDn 64
#define HHn 16
#define BBn 4
#define L2E 1.4426950408889634f

#define ROWB 144
#define KB0 0
#define KB1 18432
#define VB0 0
#define VB1 18432
#define SMEMB_P1 36864
// pass2 smem: V double buffer | stage (128 x 68 u32) | sInv (128 f32)
#define STG_OFF 36864
#define SINV_OFF (36864 + 34816)
#define SMEMB_P2 (36864 + 34816 + 512)

#define NELEM (BBn * HHn * SSn * DDn)
__device__ __half g_K16[NELEM];
__device__ __half g_V16[NELEM];
__device__ float  g_inv[BBn * HHn * SSn];
__device__ int    g_mnz;
__device__ uint32_t g_F[134217728];   // e fragments, 512 MB

__device__ __forceinline__ uint32_t smem_u32(const void* p) {
    uint32_t a;
    asm("{ .reg .u64 t; cvta.to.shared.u64 t, %1; cvt.u32.u64 %0, t; }" : "=r"(a) : "l"(p));
    return a;
}
__device__ __forceinline__ void mma16816(float* c, const uint32_t* a, const uint32_t* b) {
    asm volatile("mma.sync.aligned.m16n8k16.row.col.f32.f16.f16.f32 "
        "{%0,%1,%2,%3}, {%4,%5,%6,%7}, {%8,%9}, {%0,%1,%2,%3};"
        : "+f"(c[0]), "+f"(c[1]), "+f"(c[2]), "+f"(c[3])
        : "r"(a[0]), "r"(a[1]), "r"(a[2]), "r"(a[3]), "r"(b[0]), "r"(b[1]));
}
__device__ __forceinline__ void ldsm4(uint32_t* r, uint32_t a) {
    asm volatile("ldmatrix.sync.aligned.m8n8.x4.shared.b16 {%0,%1,%2,%3}, [%4];"
        : "=r"(r[0]), "=r"(r[1]), "=r"(r[2]), "=r"(r[3]) : "r"(a));
}
__device__ __forceinline__ void ldsm4t(uint32_t* r, uint32_t a) {
    asm volatile("ldmatrix.sync.aligned.m8n8.x4.trans.shared.b16 {%0,%1,%2,%3}, [%4];"
        : "=r"(r[0]), "=r"(r[1]), "=r"(r[2]), "=r"(r[3]) : "r"(a));
}
__device__ __forceinline__ uint32_t pack2h(float x, float y) {
    __half2 h2 = __float22half2_rn(make_float2(x, y));
    return *reinterpret_cast<uint32_t*>(&h2);
}
__device__ __forceinline__ float2 h2f(uint32_t h) {
    return __half22float2(*reinterpret_cast<__half2*>(&h));
}
__device__ __forceinline__ void split2h(float x, float y, uint32_t& hp, uint32_t& lp) {
    __half2 h2 = __float22half2_rn(make_float2(x, y));
    float2 hf = __half22float2(h2);
    __half2 l2 = __float22half2_rn(make_float2(x - hf.x, y - hf.y));
    hp = *reinterpret_cast<uint32_t*>(&h2);
    lp = *reinterpret_cast<uint32_t*>(&l2);
}
__device__ __forceinline__ float ex2(float x) {
    float y; asm("ex2.approx.f32 %0, %1;" : "=f"(y) : "f"(x)); return y;
}
#define CPA16(dst, src) \
    asm volatile("cp.async.cg.shared.global [%0], [%1], 16;" :: "r"(dst), "l"(src))
#define CPCOMMIT() asm volatile("cp.async.commit_group;")
#define CPWAIT(n)  asm volatile("cp.async.wait_group %0;" :: "n"(n))

// ---------- prologue kernels ----------
__global__ __launch_bounds__(256) void cvt_fp16(
    const float* __restrict__ K, const float* __restrict__ V)
{
    size_t i = ((size_t)blockIdx.x * 256 + threadIdx.x) * 8;
    float4 a = *(const float4*)(K + i);
    float4 b = *(const float4*)(K + i + 4);
    *(uint4*)(g_K16 + i) = make_uint4(pack2h(a.x, a.y), pack2h(a.z, a.w),
                                      pack2h(b.x, b.y), pack2h(b.z, b.w));
    a = *(const float4*)(V + i);
    b = *(const float4*)(V + i + 4);
    *(uint4*)(g_V16 + i) = make_uint4(pack2h(a.x, a.y), pack2h(a.z, a.w),
                                      pack2h(b.x, b.y), pack2h(b.z, b.w));
}
__global__ void zero_flag() { g_mnz = 0; }
__global__ __launch_bounds__(256) void chk_mask(const float* __restrict__ M)
{
    size_t i = ((size_t)blockIdx.x * 256 + threadIdx.x) * 4;
    float4 v = *(const float4*)(M + i);
    int nz = (v.x != 0.f) | (v.y != 0.f) | (v.z != 0.f) | (v.w != 0.f);
    if (__ballot_sync(0xffffffffu, nz) && (threadIdx.x & 31) == 0)
        atomicOr(&g_mnz, 1);
}

// ---------- PASS 1: rowsum inverses + fp16 exp fragments -> g_F ----------
__global__ __launch_bounds__(256, 3) void attn_pass1(
    const float* __restrict__ Q, const float* __restrict__ Bias,
    const float* __restrict__ Mask)
{
    extern __shared__ char sm[];

    const int tid = threadIdx.x, wid = tid >> 5, lane = tid & 31;
    const int b = blockIdx.x, h = blockIdx.y, qt = blockIdx.z;
    const int bh = b * HHn + h, q0 = qt * 128;
    const int rA = wid * 16 + (lane >> 2);
    const int kA = (lane & 3) * 2;
    const bool mz = (g_mnz != 0);
    const size_t tile = (size_t)bh * 16 + qt;

    uint32_t qhi[4][4];
    {
        const float* q_r0 = Q + ((size_t)bh * SSn + q0 + rA) * DDn;
        const float* q_r1 = q_r0 + 8 * DDn;
        #pragma unroll
        for (int ks = 0; ks < 4; ++ks) {
            float2 v;
            v = *(const float2*)(q_r0 + ks * 16 + kA);
            qhi[ks][0] = pack2h(v.x * 0.125f, v.y * 0.125f);
            v = *(const float2*)(q_r1 + ks * 16 + kA);
            qhi[ks][1] = pack2h(v.x * 0.125f, v.y * 0.125f);
            v = *(const float2*)(q_r0 + ks * 16 + 8 + kA);
            qhi[ks][2] = pack2h(v.x * 0.125f, v.y * 0.125f);
            v = *(const float2*)(q_r1 + ks * 16 + 8 + kA);
            qhi[ks][3] = pack2h(v.x * 0.125f, v.y * 0.125f);
        }
    }

    const uint32_t sb = smem_u32(sm);
    const __half* gK = g_K16 + (size_t)bh * SSn * DDn;
    const float* brow0 = Bias + ((size_t)h * SSn + q0 + rA) * SSn;
    const float* brow1 = brow0 + 8 * SSn;
    const float* mrow0 = Mask + ((size_t)b * SSn + q0 + rA) * SSn;
    const float* mrow1 = mrow0 + 8 * SSn;
    const int ln8 = lane & 7, lg = lane >> 3;

    auto loadK = [&](int c, uint32_t base) {
        const __half* src = gK + c * 8192;
        #pragma unroll
        for (int i = 0; i < 4; ++i) {
            int s = tid + i * 256, row = s >> 3, c8 = s & 7;
            CPA16(sb + base + (uint32_t)(row * ROWB + c8 * 16), src + row * 64 + c8 * 8);
        }
    };

    float rs0 = 0.f, rs1 = 0.f;
    loadK(0, KB0); CPCOMMIT();
    for (int c = 0; c < 16; ++c) {
        if (c < 15) { loadK(c + 1, (c & 1) ? KB0 : KB1); CPCOMMIT(); CPWAIT(1); }
        else CPWAIT(0);
        __syncthreads();

        uint32_t* cbase = g_F + ((tile * 16 + c) * 8 + wid) * 1024 + lane * 4;
        const uint32_t kb = sb + ((c & 1) ? KB1 : KB0);
        uint32_t eh01[4], eh23[4];

        #pragma unroll 4
        for (int nt = 0; nt < 16; ++nt) {
            const uint32_t ba = kb + (uint32_t)((nt * 8 + ln8) * ROWB + lg * 16);
            uint32_t bf[4][2], t4[4];
            ldsm4(t4, ba);
            bf[0][0] = t4[0]; bf[0][1] = t4[1]; bf[1][0] = t4[2]; bf[1][1] = t4[3];
            ldsm4(t4, ba + 64);
            bf[2][0] = t4[0]; bf[2][1] = t4[1]; bf[3][0] = t4[2]; bf[3][1] = t4[3];

            float cc[4] = {0.f, 0.f, 0.f, 0.f};
            #pragma unroll
            for (int ks = 0; ks < 4; ++ks) mma16816(cc, qhi[ks], bf[ks]);

            const int col = c * 128 + nt * 8 + kA;
            float2 bb0 = *(const float2*)(brow0 + col);
            float2 bb1 = *(const float2*)(brow1 + col);
            float2 mm0 = make_float2(0.f, 0.f), mm1 = make_float2(0.f, 0.f);
            if (mz) {
                mm0 = *(const float2*)(mrow0 + col);
                mm1 = *(const float2*)(mrow1 + col);
            }
            float e0 = ex2((cc[0] + bb0.x + mm0.x) * L2E);
            float e1 = ex2((cc[1] + bb0.y + mm0.y) * L2E);
            float e2 = ex2((cc[2] + bb1.x + mm1.x) * L2E);
            float e3 = ex2((cc[3] + bb1.y + mm1.y) * L2E);
            rs0 += e0 + e1;
            rs1 += e2 + e3;
            eh01[nt & 3] = pack2h(e0, e1);
            eh23[nt & 3] = pack2h(e2, e3);
            if ((nt & 3) == 3) {
                *(uint4*)(cbase + (nt >> 2) * 128) =
                    make_uint4(eh01[0], eh01[1], eh01[2], eh01[3]);
                *(uint4*)(cbase + 512 + (nt >> 2) * 128) =
                    make_uint4(eh23[0], eh23[1], eh23[2], eh23[3]);
            }
        }
        __syncthreads();
    }
    rs0 += __shfl_xor_sync(0xffffffffu, rs0, 1);
    rs0 += __shfl_xor_sync(0xffffffffu, rs0, 2);
    rs1 += __shfl_xor_sync(0xffffffffu, rs1, 1);
    rs1 += __shfl_xor_sync(0xffffffffu, rs1, 2);
    if ((lane & 3) == 0) {
        g_inv[(size_t)bh * SSn + q0 + rA] = 1.f / rs0;
        g_inv[(size_t)bh * SSn + q0 + rA + 8] = 1.f / rs1;
    }
}

// ---------- PASS 2: reload e fragments, P@V; attn written via smem transpose ----------
__global__ __launch_bounds__(256, 3) void attn_pass2(
    float* __restrict__ Out, float* __restrict__ Attn)
{
    extern __shared__ char sm[];
    uint32_t* stg = (uint32_t*)(sm + STG_OFF);
    float* sInvS = (float*)(sm + SINV_OFF);

    const int tid = threadIdx.x, wid = tid >> 5, lane = tid & 31;
    const int b = blockIdx.x, h = blockIdx.y, qt = blockIdx.z;
    const int bh = b * HHn + h, q0 = qt * 128;
    const int rA = wid * 16 + (lane >> 2);
    const int kA = (lane & 3) * 2;
    const int t = lane & 3;
    const size_t tile = (size_t)bh * 16 + qt;

    const float inv0 = g_inv[(size_t)bh * SSn + q0 + rA];
    const float inv1 = g_inv[(size_t)bh * SSn + q0 + rA + 8];
    if (tid < 128) sInvS[tid] = g_inv[(size_t)bh * SSn + q0 + tid];

    const uint32_t sb = smem_u32(sm);
    const __half* gV = g_V16 + (size_t)bh * SSn * DDn;

    const int ln8 = lane & 7;
    const int lg1 = (lane >> 3) & 1, lg2 = lane >> 4;

    auto loadV = [&](int c, uint32_t base) {
        const __half* src = gV + c * 8192;
        #pragma unroll
        for (int i = 0; i < 4; ++i) {
            int s = tid + i * 256, row = s >> 3, c8 = s & 7;
            CPA16(sb + base + (uint32_t)(row * ROWB + c8 * 16), src + row * 64 + c8 * 8);
        }
    };

    float acc[8][4];
    #pragma unroll
    for (int n = 0; n < 8; ++n)
        #pragma unroll
        for (int j = 0; j < 4; ++j) acc[n][j] = 0.f;

    loadV(0, VB0); CPCOMMIT();
    for (int c = 0; c < 16; ++c) {
        // e-fragment loads for this chunk (coalesced LDG.128)
        const uint32_t* cb = g_F + ((tile * 16 + c) * 8 + wid) * 1024 + lane * 4;
        uint32_t e01[16], e23[16];
        #pragma unroll
        for (int j = 0; j < 4; ++j) {
            uint4 v = *(const uint4*)(cb + j * 128);
            e01[4*j] = v.x; e01[4*j+1] = v.y; e01[4*j+2] = v.z; e01[4*j+3] = v.w;
            v = *(const uint4*)(cb + 512 + j * 128);
            e23[4*j] = v.x; e23[4*j+1] = v.y; e23[4*j+2] = v.z; e23[4*j+3] = v.w;
        }

        if (c < 15) { loadV(c + 1, (c & 1) ? VB0 : VB1); CPCOMMIT(); CPWAIT(1); }
        else CPWAIT(0);
        __syncthreads();   // V(c) ready; stage free (drained last chunk)

        // ---- stage e into smem transpose buffer (conflict-free STS.32)
        #pragma unroll
        for (int nt = 0; nt < 16; ++nt) {
            stg[rA * 68 + nt * 4 + t] = e01[nt];
            stg[(rA + 8) * 68 + nt * 4 + t] = e23[nt];
        }

        const uint32_t vb = sb + ((c & 1) ? VB1 : VB0);

        #pragma unroll
        for (int ks = 0; ks < 8; ++ks) {         // 16-key groups
            const int nt0 = 2 * ks, nt1 = 2 * ks + 1;
            float2 fa = h2f(e01[nt0]), fb = h2f(e23[nt0]);
            float2 fc = h2f(e01[nt1]), fd = h2f(e23[nt1]);
            float p0 = fa.x * inv0, p1 = fa.y * inv0;
            float p2 = fb.x * inv1, p3 = fb.y * inv1;
            float p4 = fc.x * inv0, p5 = fc.y * inv0;
            float p6 = fd.x * inv1, p7 = fd.y * inv1;

            uint32_t phi[4], plo[4];
            split2h(p0, p1, phi[0], plo[0]);
            split2h(p2, p3, phi[1], plo[1]);
            split2h(p4, p5, phi[2], plo[2]);
            split2h(p6, p7, phi[3], plo[3]);

            const uint32_t ka = vb + (uint32_t)((ks * 16 + lg1 * 8 + ln8) * ROWB + lg2 * 16);
            #pragma unroll
            for (int np = 0; np < 4; ++np) {
                uint32_t t4[4];
                ldsm4t(t4, ka + np * 32);       // V fp16 : d-tiles 2np, 2np+1
                mma16816(acc[2 * np],     phi, &t4[0]);
                mma16816(acc[2 * np + 1], phi, &t4[2]);
                mma16816(acc[2 * np],     plo, &t4[0]);
                mma16816(acc[2 * np + 1], plo, &t4[2]);
            }
        }
        __syncthreads();   // stage fully written by all warps

        // ---- drain: coalesced LDS.128 + STG.128 of attn = h2f(e) * inv
        {
            float* abase = Attn + ((size_t)bh * SSn + q0) * SSn + c * 128;
            #pragma unroll
            for (int s = 0; s < 8; ++s) {
                int idx = tid + s * 256;          // 0..2047
                int row = idx >> 4;               // 0..127
                int j0 = (idx & 15) * 4;          // u32 col within chunk
                const uint32_t* sp = stg + row * 68 + j0;
                uint4 u = *(const uint4*)sp;
                const float iv = sInvS[row];
                float2 f0 = h2f(u.x), f1 = h2f(u.y), f2 = h2f(u.z), f3 = h2f(u.w);
                float4* dst = (float4*)(abase + (size_t)row * SSn + j0 * 2);
                dst[0] = make_float4(f0.x * iv, f0.y * iv, f1.x * iv, f1.y * iv);
                dst[1] = make_float4(f2.x * iv, f2.y * iv, f3.x * iv, f3.y * iv);
            }
        }
    }

    float* orow0 = Out + ((size_t)bh * SSn + q0 + rA) * DDn;
    float* orow1 = orow0 + 8 * DDn;
    #pragma unroll
    for (int nt = 0; nt < 8; ++nt) {
        *(float2*)(orow0 + nt * 8 + kA) = make_float2(acc[nt][0], acc[nt][1]);
        *(float2*)(orow1 + nt * 8 + kA) = make_float2(acc[nt][2], acc[nt][3]);
    }
}

extern "C" void kernel_launch(void* const* d_in, const int* in_sizes, int n_in,
                              void* d_out, int out_size)
{
    const float* Q    = (const float*)d_in[0];
    const float* K    = (const float*)d_in[1];
    const float* V    = (const float*)d_in[2];
    const float* Bias = (const float*)d_in[3];
    const float* Mask = (const float*)d_in[4];
    float* Out  = (float*)d_out;
    float* Attn = Out + (size_t)BBn * HHn * SSn * DDn;

    zero_flag<<<1, 1>>>();
    chk_mask<<<(BBn * SSn * SSn) / (256 * 4), 256>>>(Mask);
    cvt_fp16<<<NELEM / (256 * 8), 256>>>(K, V);

    cudaFuncSetAttribute(attn_pass1, cudaFuncAttributeMaxDynamicSharedMemorySize, SMEMB_P1);
    cudaFuncSetAttribute(attn_pass2, cudaFuncAttributeMaxDynamicSharedMemorySize, SMEMB_P2);

    dim3 grid(BBn, HHn, SSn / 128);
    attn_pass1<<<grid, 256, SMEMB_P1>>>(Q, Bias, Mask);
    attn_pass2<<<grid, 256, SMEMB_P2>>>(Out, Attn);
}

// round 17
// speedup vs baseline: 1.1584x; 1.1584x over previous
#include <cuda_runtime.h>
#include <cuda_fp16.h>
#include <cstdint>

#define SSn 2048
#define DDn 64
#define HHn 16
#define BBn 4
#define L2E 1.4426950408889634f

#define ROWB 144
#define KB0 0
#define KB1 18432
#define VB0 0
#define VB1 18432
#define SMEMB_P1 36864
#define SMEMB_P2 36864

#define NELEM (BBn * HHn * SSn * DDn)
__device__ __half g_K16[NELEM];
__device__ __half g_V16[NELEM];
__device__ float  g_inv[BBn * HHn * SSn];
__device__ int    g_mnz;
__device__ uint32_t g_F[134217728];   // e fragments, 512 MB
__device__ uint32_t g_B[33554432];    // bias fp16 fragments, 134 MB (no b dim)

__device__ __forceinline__ uint32_t smem_u32(const void* p) {
    uint32_t a;
    asm("{ .reg .u64 t; cvta.to.shared.u64 t, %1; cvt.u32.u64 %0, t; }" : "=r"(a) : "l"(p));
    return a;
}
__device__ __forceinline__ void mma16816(float* c, const uint32_t* a, const uint32_t* b) {
    asm volatile("mma.sync.aligned.m16n8k16.row.col.f32.f16.f16.f32 "
        "{%0,%1,%2,%3}, {%4,%5,%6,%7}, {%8,%9}, {%0,%1,%2,%3};"
        : "+f"(c[0]), "+f"(c[1]), "+f"(c[2]), "+f"(c[3])
        : "r"(a[0]), "r"(a[1]), "r"(a[2]), "r"(a[3]), "r"(b[0]), "r"(b[1]));
}
__device__ __forceinline__ void ldsm4(uint32_t* r, uint32_t a) {
    asm volatile("ldmatrix.sync.aligned.m8n8.x4.shared.b16 {%0,%1,%2,%3}, [%4];"
        : "=r"(r[0]), "=r"(r[1]), "=r"(r[2]), "=r"(r[3]) : "r"(a));
}
__device__ __forceinline__ void ldsm4t(uint32_t* r, uint32_t a) {
    asm volatile("ldmatrix.sync.aligned.m8n8.x4.trans.shared.b16 {%0,%1,%2,%3}, [%4];"
        : "=r"(r[0]), "=r"(r[1]), "=r"(r[2]), "=r"(r[3]) : "r"(a));
}
__device__ __forceinline__ uint32_t pack2h(float x, float y) {
    __half2 h2 = __float22half2_rn(make_float2(x, y));
    return *reinterpret_cast<uint32_t*>(&h2);
}
__device__ __forceinline__ float2 h2f(uint32_t h) {
    return __half22float2(*reinterpret_cast<__half2*>(&h));
}
__device__ __forceinline__ void split2h(float x, float y, uint32_t& hp, uint32_t& lp) {
    __half2 h2 = __float22half2_rn(make_float2(x, y));
    float2 hf = __half22float2(h2);
    __half2 l2 = __float22half2_rn(make_float2(x - hf.x, y - hf.y));
    hp = *reinterpret_cast<uint32_t*>(&h2);
    lp = *reinterpret_cast<uint32_t*>(&l2);
}
__device__ __forceinline__ float ex2(float x) {
    float y; asm("ex2.approx.f32 %0, %1;" : "=f"(y) : "f"(x)); return y;
}
#define CPA16(dst, src) \
    asm volatile("cp.async.cg.shared.global [%0], [%1], 16;" :: "r"(dst), "l"(src))
#define CPCOMMIT() asm volatile("cp.async.commit_group;")
#define CPWAIT(n)  asm volatile("cp.async.wait_group %0;" :: "n"(n))

// ---------- prologue kernels ----------
__global__ __launch_bounds__(256) void cvt_fp16(
    const float* __restrict__ K, const float* __restrict__ V)
{
    size_t i = ((size_t)blockIdx.x * 256 + threadIdx.x) * 8;
    float4 a = *(const float4*)(K + i);
    float4 b = *(const float4*)(K + i + 4);
    *(uint4*)(g_K16 + i) = make_uint4(pack2h(a.x, a.y), pack2h(a.z, a.w),
                                      pack2h(b.x, b.y), pack2h(b.z, b.w));
    a = *(const float4*)(V + i);
    b = *(const float4*)(V + i + 4);
    *(uint4*)(g_V16 + i) = make_uint4(pack2h(a.x, a.y), pack2h(a.z, a.w),
                                      pack2h(b.x, b.y), pack2h(b.z, b.w));
}
__global__ void zero_flag() { g_mnz = 0; }
__global__ __launch_bounds__(256) void chk_mask(const float* __restrict__ M)
{
    size_t i = ((size_t)blockIdx.x * 256 + threadIdx.x) * 4;
    float4 v = *(const float4*)(M + i);
    int nz = (v.x != 0.f) | (v.y != 0.f) | (v.z != 0.f) | (v.w != 0.f);
    if (__ballot_sync(0xffffffffu, nz) && (threadIdx.x & 31) == 0)
        atomicOr(&g_mnz, 1);
}

// ---------- bias -> fp16 fragment-layout transpose ----------
// grid (x=c, y=qt, z=h); 256 threads; tile = 128 q-rows x 128 cols
__global__ __launch_bounds__(256) void bias_transpose(const float* __restrict__ Bias)
{
    __shared__ uint32_t stg[128 * 68];
    const int tid = threadIdx.x;
    const int c = blockIdx.x, qt = blockIdx.y, h = blockIdx.z;
    const int q0 = qt * 128;

    #pragma unroll
    for (int i = 0; i < 16; ++i) {
        int idx = tid + i * 256;            // 0..4095 float4
        int row = idx >> 5, c4 = idx & 31;  // 32 float4 per row
        float4 v = *(const float4*)(Bias + ((size_t)h * SSn + q0 + row) * SSn
                                    + c * 128 + c4 * 4);
        stg[row * 68 + c4 * 2]     = pack2h(v.x, v.y);
        stg[row * 68 + c4 * 2 + 1] = pack2h(v.z, v.w);
    }
    __syncthreads();

    const int w = tid >> 5, l = tid & 31;
    const int rw = w * 16 + (l >> 2), t = l & 3;
    uint32_t* gb = g_B + ((((size_t)h * 16 + qt) * 16 + c) * 8 + w) * 1024 + l * 4;
    #pragma unroll
    for (int g = 0; g < 4; ++g) {
        uint4 o01, o23;
        o01.x = stg[rw * 68 + (4*g+0)*4 + t];  o01.y = stg[rw * 68 + (4*g+1)*4 + t];
        o01.z = stg[rw * 68 + (4*g+2)*4 + t];  o01.w = stg[rw * 68 + (4*g+3)*4 + t];
        o23.x = stg[(rw+8) * 68 + (4*g+0)*4 + t];  o23.y = stg[(rw+8) * 68 + (4*g+1)*4 + t];
        o23.z = stg[(rw+8) * 68 + (4*g+2)*4 + t];  o23.w = stg[(rw+8) * 68 + (4*g+3)*4 + t];
        *(uint4*)(gb + g * 128) = o01;
        *(uint4*)(gb + 512 + g * 128) = o23;
    }
}

// ---------- PASS 1: rowsum inverses + fp16 exp fragments -> g_F ----------
__global__ __launch_bounds__(256, 3) void attn_pass1(
    const float* __restrict__ Q, const float* __restrict__ Mask)
{
    extern __shared__ char sm[];

    const int tid = threadIdx.x, wid = tid >> 5, lane = tid & 31;
    const int b = blockIdx.x, h = blockIdx.y, qt = blockIdx.z;
    const int bh = b * HHn + h, q0 = qt * 128;
    const int rA = wid * 16 + (lane >> 2);
    const int kA = (lane & 3) * 2;
    const bool mz = (g_mnz != 0);
    const size_t tile = (size_t)bh * 16 + qt;

    uint32_t qhi[4][4];
    {
        const float* q_r0 = Q + ((size_t)bh * SSn + q0 + rA) * DDn;
        const float* q_r1 = q_r0 + 8 * DDn;
        #pragma unroll
        for (int ks = 0; ks < 4; ++ks) {
            float2 v;
            v = *(const float2*)(q_r0 + ks * 16 + kA);
            qhi[ks][0] = pack2h(v.x * 0.125f, v.y * 0.125f);
            v = *(const float2*)(q_r1 + ks * 16 + kA);
            qhi[ks][1] = pack2h(v.x * 0.125f, v.y * 0.125f);
            v = *(const float2*)(q_r0 + ks * 16 + 8 + kA);
            qhi[ks][2] = pack2h(v.x * 0.125f, v.y * 0.125f);
            v = *(const float2*)(q_r1 + ks * 16 + 8 + kA);
            qhi[ks][3] = pack2h(v.x * 0.125f, v.y * 0.125f);
        }
    }

    const uint32_t sb = smem_u32(sm);
    const __half* gK = g_K16 + (size_t)bh * SSn * DDn;
    const float* mrow0 = Mask + ((size_t)b * SSn + q0 + rA) * SSn;
    const float* mrow1 = mrow0 + 8 * SSn;
    const uint32_t* gbT = g_B + ((((size_t)h * 16 + qt) * 16) * 8 + wid) * 1024 + lane * 4;
    const int ln8 = lane & 7, lg = lane >> 3;

    auto loadK = [&](int c, uint32_t base) {
        const __half* src = gK + c * 8192;
        #pragma unroll
        for (int i = 0; i < 4; ++i) {
            int s = tid + i * 256, row = s >> 3, c8 = s & 7;
            CPA16(sb + base + (uint32_t)(row * ROWB + c8 * 16), src + row * 64 + c8 * 8);
        }
    };

    float rs0 = 0.f, rs1 = 0.f;
    loadK(0, KB0); CPCOMMIT();
    for (int c = 0; c < 16; ++c) {
        if (c < 15) { loadK(c + 1, (c & 1) ? KB0 : KB1); CPCOMMIT(); CPWAIT(1); }
        else CPWAIT(0);
        __syncthreads();

        uint32_t* cbase = g_F + ((tile * 16 + c) * 8 + wid) * 1024 + lane * 4;
        const uint32_t* gb = gbT + (size_t)c * 8192;   // next chunk block (stride 8*1024)
        const uint32_t kb = sb + ((c & 1) ? KB1 : KB0);
        uint32_t eh01[4], eh23[4];
        uint4 b01q, b23q;

        #pragma unroll 4
        for (int nt = 0; nt < 16; ++nt) {
            if ((nt & 3) == 0) {
                b01q = *(const uint4*)(gb + (nt >> 2) * 128);
                b23q = *(const uint4*)(gb + 512 + (nt >> 2) * 128);
            }
            const uint32_t ba = kb + (uint32_t)((nt * 8 + ln8) * ROWB + lg * 16);
            uint32_t bf[4][2], t4[4];
            ldsm4(t4, ba);
            bf[0][0] = t4[0]; bf[0][1] = t4[1]; bf[1][0] = t4[2]; bf[1][1] = t4[3];
            ldsm4(t4, ba + 64);
            bf[2][0] = t4[0]; bf[2][1] = t4[1]; bf[3][0] = t4[2]; bf[3][1] = t4[3];

            float cc[4] = {0.f, 0.f, 0.f, 0.f};
            #pragma unroll
            for (int ks = 0; ks < 4; ++ks) mma16816(cc, qhi[ks], bf[ks]);

            float2 bb0 = h2f(((const uint32_t*)&b01q)[nt & 3]);
            float2 bb1 = h2f(((const uint32_t*)&b23q)[nt & 3]);
            float2 mm0 = make_float2(0.f, 0.f), mm1 = make_float2(0.f, 0.f);
            if (mz) {
                const int col = c * 128 + nt * 8 + kA;
                mm0 = *(const float2*)(mrow0 + col);
                mm1 = *(const float2*)(mrow1 + col);
            }
            float e0 = ex2((cc[0] + bb0.x + mm0.x) * L2E);
            float e1 = ex2((cc[1] + bb0.y + mm0.y) * L2E);
            float e2 = ex2((cc[2] + bb1.x + mm1.x) * L2E);
            float e3 = ex2((cc[3] + bb1.y + mm1.y) * L2E);
            rs0 += e0 + e1;
            rs1 += e2 + e3;
            eh01[nt & 3] = pack2h(e0, e1);
            eh23[nt & 3] = pack2h(e2, e3);
            if ((nt & 3) == 3) {
                *(uint4*)(cbase + (nt >> 2) * 128) =
                    make_uint4(eh01[0], eh01[1], eh01[2], eh01[3]);
                *(uint4*)(cbase + 512 + (nt >> 2) * 128) =
                    make_uint4(eh23[0], eh23[1], eh23[2], eh23[3]);
            }
        }
        __syncthreads();
    }
    rs0 += __shfl_xor_sync(0xffffffffu, rs0, 1);
    rs0 += __shfl_xor_sync(0xffffffffu, rs0, 2);
    rs1 += __shfl_xor_sync(0xffffffffu, rs1, 1);
    rs1 += __shfl_xor_sync(0xffffffffu, rs1, 2);
    if ((lane & 3) == 0) {
        g_inv[(size_t)bh * SSn + q0 + rA] = 1.f / rs0;
        g_inv[(size_t)bh * SSn + q0 + rA + 8] = 1.f / rs1;
    }
}

// ---------- PASS 2 (round-15 form): reload e fragments, normalize, write attn, P@V ----------
__global__ __launch_bounds__(256, 3) void attn_pass2(
    float* __restrict__ Out, float* __restrict__ Attn)
{
    extern __shared__ char sm[];

    const int tid = threadIdx.x, wid = tid >> 5, lane = tid & 31;
    const int b = blockIdx.x, h = blockIdx.y, qt = blockIdx.z;
    const int bh = b * HHn + h, q0 = qt * 128;
    const int rA = wid * 16 + (lane >> 2);
    const int kA = (lane & 3) * 2;
    const size_t tile = (size_t)bh * 16 + qt;

    const float inv0 = g_inv[(size_t)bh * SSn + q0 + rA];
    const float inv1 = g_inv[(size_t)bh * SSn + q0 + rA + 8];

    const uint32_t sb = smem_u32(sm);
    const __half* gV = g_V16 + (size_t)bh * SSn * DDn;
    float* arow0 = Attn + ((size_t)bh * SSn + q0 + rA) * SSn;
    float* arow1 = arow0 + 8 * SSn;

    const int ln8 = lane & 7;
    const int lg1 = (lane >> 3) & 1, lg2 = lane >> 4;

    auto loadV = [&](int c, uint32_t base) {
        const __half* src = gV + c * 8192;
        #pragma unroll
        for (int i = 0; i < 4; ++i) {
            int s = tid + i * 256, row = s >> 3, c8 = s & 7;
            CPA16(sb + base + (uint32_t)(row * ROWB + c8 * 16), src + row * 64 + c8 * 8);
        }
    };

    float acc[8][4];
    #pragma unroll
    for (int n = 0; n < 8; ++n)
        #pragma unroll
        for (int j = 0; j < 4; ++j) acc[n][j] = 0.f;

    loadV(0, VB0); CPCOMMIT();
    for (int c = 0; c < 16; ++c) {
        const uint32_t* cb = g_F + ((tile * 16 + c) * 8 + wid) * 1024 + lane * 4;
        uint32_t e01[16], e23[16];
        #pragma unroll
        for (int j = 0; j < 4; ++j) {
            uint4 v = *(const uint4*)(cb + j * 128);
            e01[4*j] = v.x; e01[4*j+1] = v.y; e01[4*j+2] = v.z; e01[4*j+3] = v.w;
            v = *(const uint4*)(cb + 512 + j * 128);
            e23[4*j] = v.x; e23[4*j+1] = v.y; e23[4*j+2] = v.z; e23[4*j+3] = v.w;
        }

        if (c < 15) { loadV(c + 1, (c & 1) ? VB0 : VB1); CPCOMMIT(); CPWAIT(1); }
        else CPWAIT(0);
        __syncthreads();

        const uint32_t vb = sb + ((c & 1) ? VB1 : VB0);

        #pragma unroll
        for (int ks = 0; ks < 8; ++ks) {
            const int nt0 = 2 * ks, nt1 = 2 * ks + 1;
            float2 fa = h2f(e01[nt0]), fb = h2f(e23[nt0]);
            float2 fc = h2f(e01[nt1]), fd = h2f(e23[nt1]);
            float p0 = fa.x * inv0, p1 = fa.y * inv0;
            float p2 = fb.x * inv1, p3 = fb.y * inv1;
            float p4 = fc.x * inv0, p5 = fc.y * inv0;
            float p6 = fd.x * inv1, p7 = fd.y * inv1;

            const int col0 = c * 128 + nt0 * 8 + kA;
            *(float2*)(arow0 + col0)     = make_float2(p0, p1);
            *(float2*)(arow1 + col0)     = make_float2(p2, p3);
            *(float2*)(arow0 + col0 + 8) = make_float2(p4, p5);
            *(float2*)(arow1 + col0 + 8) = make_float2(p6, p7);

            uint32_t phi[4], plo[4];
            split2h(p0, p1, phi[0], plo[0]);
            split2h(p2, p3, phi[1], plo[1]);
            split2h(p4, p5, phi[2], plo[2]);
            split2h(p6, p7, phi[3], plo[3]);

            const uint32_t ka = vb + (uint32_t)((ks * 16 + lg1 * 8 + ln8) * ROWB + lg2 * 16);
            #pragma unroll
            for (int np = 0; np < 4; ++np) {
                uint32_t t4[4];
                ldsm4t(t4, ka + np * 32);
                mma16816(acc[2 * np],     phi, &t4[0]);
                mma16816(acc[2 * np + 1], phi, &t4[2]);
                mma16816(acc[2 * np],     plo, &t4[0]);
                mma16816(acc[2 * np + 1], plo, &t4[2]);
            }
        }
        __syncthreads();
    }

    float* orow0 = Out + ((size_t)bh * SSn + q0 + rA) * DDn;
    float* orow1 = orow0 + 8 * DDn;
    #pragma unroll
    for (int nt = 0; nt < 8; ++nt) {
        *(float2*)(orow0 + nt * 8 + kA) = make_float2(acc[nt][0], acc[nt][1]);
        *(float2*)(orow1 + nt * 8 + kA) = make_float2(acc[nt][2], acc[nt][3]);
    }
}

extern "C" void kernel_launch(void* const* d_in, const int* in_sizes, int n_in,
                              void* d_out, int out_size)
{
    const float* Q    = (const float*)d_in[0];
    const float* K    = (const float*)d_in[1];
    const float* V    = (const float*)d_in[2];
    const float* Bias = (const float*)d_in[3];
    const float* Mask = (const float*)d_in[4];
    float* Out  = (float*)d_out;
    float* Attn = Out + (size_t)BBn * HHn * SSn * DDn;

    zero_flag<<<1, 1>>>();
    chk_mask<<<(BBn * SSn * SSn) / (256 * 4), 256>>>(Mask);
    cvt_fp16<<<NELEM / (256 * 8), 256>>>(K, V);
    bias_transpose<<<dim3(16, 16, 16), 256>>>(Bias);

    cudaFuncSetAttribute(attn_pass1, cudaFuncAttributeMaxDynamicSharedMemorySize, SMEMB_P1);
    cudaFuncSetAttribute(attn_pass2, cudaFuncAttributeMaxDynamicSharedMemorySize, SMEMB_P2);

    dim3 grid(BBn, HHn, SSn / 128);
    attn_pass1<<<grid, 256, SMEMB_P1>>>(Q, Mask);
    attn_pass2<<<grid, 256, SMEMB_P2>>>(Out, Attn);
}